// round 2
// baseline (speedup 1.0000x reference)
#include <cuda_runtime.h>
#include <cuda_bf16.h>
#include <mma.h>

using namespace nvcuda;

#define NROWS 8192
#define DIMS  512
#define BM 128
#define BN 128
#define BK 64
#define NBLK (NROWS / BM)                 /* 64 */
#define NTILES (NBLK * (NBLK + 1) / 2)    /* 2080 upper-triangular tiles */
#define PAD_K 80                          /* bf16 elems per smem tile row (16B-aligned vec stores) */
#define PAD_E 132                         /* fp32 elems per epilogue smem row (mult of 4) */
#define SMEM_BYTES (BM * PAD_E * 4)       /* 67584 B: epilogue tile; A/B stage (40960 B) aliases it */

// Scratch (device globals only — no allocation allowed)
__device__ __nv_bfloat16 g_A[NROWS * DIMS];   // normalized reps, bf16
__device__ float g_pos[NROWS];                // sum of scores over same-label j (j != i)
__device__ float g_neg[NROWS];                // sum of exp(score) over diff-label j
__device__ int   g_lab[NROWS];
__device__ int   g_cnt[1024];                 // class histogram

__global__ void k_init() {
    int i = blockIdx.x * blockDim.x + threadIdx.x;
    if (i < NROWS) { g_pos[i] = 0.0f; g_neg[i] = 0.0f; }
    if (i < 1024)  g_cnt[i] = 0;
}

// Decode labels (int64 vs int32 sniffed by content) + class histogram. One block.
__global__ void k_lab(const unsigned int* __restrict__ raw) {
    __shared__ int is64;
    if (threadIdx.x == 0) {
        unsigned int nz = 0;
        for (int i = 1; i < 256; i += 2) nz |= raw[i];   // int64 high words are 0 for labels in [0,100)
        is64 = (nz == 0u) ? 1 : 0;
    }
    __syncthreads();
    int w64 = is64;
    for (int i = threadIdx.x; i < NROWS; i += blockDim.x) {
        int v = w64 ? (int)raw[2 * i] : (int)raw[i];
        v &= 1023;
        g_lab[i] = v;
        atomicAdd(&g_cnt[v], 1);
    }
}

// Row L2-normalize fp32 -> bf16. One block per row, 128 threads, float4 loads.
__global__ void k_norm(const float* __restrict__ reps) {
    int row = blockIdx.x;
    const float4* rp = (const float4*)(reps + (size_t)row * DIMS);
    float4 v = rp[threadIdx.x];
    float ss = v.x * v.x + v.y * v.y + v.z * v.z + v.w * v.w;
    #pragma unroll
    for (int o = 16; o; o >>= 1) ss += __shfl_xor_sync(0xffffffffu, ss, o);
    __shared__ float ws[4];
    if ((threadIdx.x & 31) == 0) ws[threadIdx.x >> 5] = ss;
    __syncthreads();
    float tot = ws[0] + ws[1] + ws[2] + ws[3];
    float inv = 1.0f / sqrtf(tot);     // norms ~22.6, the 1e-8 clamp in the reference is inert
    __nv_bfloat162 p0 = __floats2bfloat162_rn(v.x * inv, v.y * inv);
    __nv_bfloat162 p1 = __floats2bfloat162_rn(v.z * inv, v.w * inv);
    __nv_bfloat162* op = (__nv_bfloat162*)(g_A + (size_t)row * DIMS + threadIdx.x * 4);
    op[0] = p0; op[1] = p1;
}

// Fused tile kernel: bf16 wmma GEMM (cos tile) -> score -> label-masked pos/neg
// partial sums for rows (and columns, exploiting symmetry) -> atomic scatter.
extern __shared__ char smem_raw[];

__global__ void __launch_bounds__(256, 2) k_gemm() {
    // Linear block -> upper-triangular (bi, bj), bi <= bj
    int b = blockIdx.x;
    int bi = 0, rem = b;
    while (rem >= NBLK - bi) { rem -= NBLK - bi; ++bi; }
    int bj = bi + rem;

    __nv_bfloat16* sA = (__nv_bfloat16*)smem_raw;
    __nv_bfloat16* sB = sA + BM * PAD_K;
    float* sE = (float*)smem_raw;          // aliases sA/sB (guarded by syncs)
    __shared__ int labr[BM], labc[BN];

    int tid = threadIdx.x;
    if (tid < 128) labr[tid] = g_lab[bi * BM + tid];
    else           labc[tid - 128] = g_lab[bj * BN + (tid - 128)];

    int w  = tid >> 5;
    int wm = w & 3;        // 4 warp rows  (32 rows each)
    int wn = w >> 2;       // 2 warp cols  (64 cols each)

    wmma::fragment<wmma::accumulator, 16, 16, 16, float> acc[2][4];
    #pragma unroll
    for (int m = 0; m < 2; ++m)
        #pragma unroll
        for (int n = 0; n < 4; ++n)
            wmma::fill_fragment(acc[m][n], 0.0f);

    const __nv_bfloat16* Arow = g_A + (size_t)bi * BM * DIMS;
    const __nv_bfloat16* Brow = g_A + (size_t)bj * BN * DIMS;

    for (int kc = 0; kc < DIMS; kc += BK) {
        __syncthreads();   // guard previous stage/epilogue aliasing
        #pragma unroll
        for (int p = 0; p < 4; ++p) {
            int v  = tid + p * 256;      // 0..1023
            int r  = v >> 3;             // 0..127
            int c8 = (v & 7) * 8;        // 0..56
            *(uint4*)&sA[r * PAD_K + c8] = *(const uint4*)&Arow[(size_t)r * DIMS + kc + c8];
            *(uint4*)&sB[r * PAD_K + c8] = *(const uint4*)&Brow[(size_t)r * DIMS + kc + c8];
        }
        __syncthreads();
        #pragma unroll
        for (int kk = 0; kk < BK; kk += 16) {
            wmma::fragment<wmma::matrix_a, 16, 16, 16, __nv_bfloat16, wmma::row_major> af[2];
            wmma::fragment<wmma::matrix_b, 16, 16, 16, __nv_bfloat16, wmma::col_major> bf[4];
            #pragma unroll
            for (int m = 0; m < 2; ++m)
                wmma::load_matrix_sync(af[m], &sA[(wm * 32 + m * 16) * PAD_K + kk], PAD_K);
            #pragma unroll
            for (int n = 0; n < 4; ++n)
                wmma::load_matrix_sync(bf[n], &sB[(wn * 64 + n * 16) * PAD_K + kk], PAD_K);
            #pragma unroll
            for (int m = 0; m < 2; ++m)
                #pragma unroll
                for (int n = 0; n < 4; ++n)
                    wmma::mma_sync(acc[m][n], af[m], bf[n], acc[m][n]);
        }
    }

    __syncthreads();
    #pragma unroll
    for (int m = 0; m < 2; ++m)
        #pragma unroll
        for (int n = 0; n < 4; ++n)
            wmma::store_matrix_sync(&sE[(wm * 32 + m * 16) * PAD_E + wn * 64 + n * 16],
                                    acc[m][n], PAD_E, wmma::mem_row_major);
    __syncthreads();

    // Phase A: row contributions (rows of block bi; this tile's 128 columns)
    {
        int r = tid & 127, h = tid >> 7;
        int gi = bi * BM + r;
        int lr = labr[r];
        float pos = 0.0f, neg = 0.0f;
        int cbase = h * 64;
        bool isdiag = (bi == bj);
        #pragma unroll 8
        for (int k = 0; k < 64; ++k) {
            int c = cbase + k;
            float cosv = sE[r * PAD_E + c];
            float s = 5.0f * (1.0f + cosv) + 1e-7f;   // ((1+cos)/2 + EPS)/TEMP, M = 0
            if (!(isdiag && r == c)) {
                if (lr == labc[c]) pos += s;
                else               neg += __expf(s);
            }
        }
        atomicAdd(&g_pos[gi], pos);
        atomicAdd(&g_neg[gi], neg);
    }

    // Phase B: column contributions via symmetry (rows of block bj), off-diag tiles only
    if (bi != bj) {
        int c = tid & 127, h = tid >> 7;
        int gj = bj * BN + c;
        int lc = labc[c];
        float pos = 0.0f, neg = 0.0f;
        int rbase = h * 64;
        #pragma unroll 8
        for (int k = 0; k < 64; ++k) {
            int r = rbase + k;
            float cosv = sE[r * PAD_E + c];
            float s = 5.0f * (1.0f + cosv) + 1e-7f;
            if (labr[r] == lc) pos += s;
            else               neg += __expf(s);
        }
        atomicAdd(&g_pos[gj], pos);
        atomicAdd(&g_neg[gj], neg);
    }
}

// Per-row loss + masked mean. Single block, tree reduction.
__global__ void k_final(float* __restrict__ out) {
    __shared__ float sl[256], sm[256];
    float lsum = 0.0f, msum = 0.0f;
    for (int i = threadIdx.x; i < NROWS; i += 256) {
        float cnt  = (float)(g_cnt[g_lab[i]] - 1);
        float posr = g_pos[i] / (cnt + 1e-8f);
        float loss = -posr + logf(g_neg[i] + 1e-8f);
        if (loss > 0.0f) { lsum += loss; msum += 1.0f; }
    }
    sl[threadIdx.x] = lsum; sm[threadIdx.x] = msum;
    __syncthreads();
    #pragma unroll
    for (int o = 128; o; o >>= 1) {
        if (threadIdx.x < o) { sl[threadIdx.x] += sl[threadIdx.x + o]; sm[threadIdx.x] += sm[threadIdx.x + o]; }
        __syncthreads();
    }
    if (threadIdx.x == 0) out[0] = sl[0] / (sm[0] + 1e-8f);
}

extern "C" void kernel_launch(void* const* d_in, const int* in_sizes, int n_in,
                              void* d_out, int out_size) {
    const float* reps = (const float*)d_in[0];
    const unsigned int* labraw = (const unsigned int*)d_in[1];
    float* out = (float*)d_out;

    cudaFuncSetAttribute(k_gemm, cudaFuncAttributeMaxDynamicSharedMemorySize, SMEM_BYTES);

    k_init<<<(NROWS + 255) / 256, 256>>>();
    k_lab<<<1, 1024>>>(labraw);
    k_norm<<<NROWS, 128>>>(reps);
    k_gemm<<<NTILES, 256, SMEM_BYTES>>>();
    k_final<<<1, 256>>>(out);
}

// round 4
// speedup vs baseline: 1.3152x; 1.3152x over previous
#include <cuda_runtime.h>
#include <cuda_bf16.h>
#include <mma.h>
#include <cstdint>

using namespace nvcuda;

#define NROWS 8192
#define DIMS  512
#define BM    128
#define BK    64
#define NBLK  64                          /* 8192/128 */
#define NTILES 2080                       /* upper-triangular 64*65/2 */
#define PAD_K 72                          /* bf16 elems/row: 144B -> LDSM conflict-free */
#define PAD_E 132                         /* fp32 elems/row for epilogue (mult of 4) */
#define STAGE_BYTES (2 * BM * PAD_K * 2)  /* A+B per stage: 36864 B */
#define DSMEM (2 * STAGE_BYTES)           /* 73728 B; epilogue tile (67584 B) aliases */

// ---------------- device scratch (no allocation allowed) ----------------
__device__ __nv_bfloat16 g_A[NROWS * DIMS];   // normalized reps, bf16
__device__ float g_pos[NROWS];
__device__ float g_neg[NROWS];
__device__ int   g_lab[NROWS];
__device__ int   g_cnt[1024];

// ---------------- helpers ----------------
__device__ __forceinline__ uint32_t smem_u32(const void* p) {
    uint32_t a;
    asm("{ .reg .u64 t; cvta.to.shared.u64 t, %1; cvt.u32.u64 %0, t; }" : "=r"(a) : "l"(p));
    return a;
}
__device__ __forceinline__ void cp16(uint32_t dst, const void* src) {
    asm volatile("cp.async.cg.shared.global [%0], [%1], 16;" :: "r"(dst), "l"(src));
}
#define CP_COMMIT() asm volatile("cp.async.commit_group;" ::: "memory")
#define CP_WAIT1()  asm volatile("cp.async.wait_group 1;" ::: "memory")
#define CP_WAIT0()  asm volatile("cp.async.wait_group 0;" ::: "memory")

// fast exp(s): s in [-0.05, 10.1]; rel err ~6e-5. FMA/ALU pipes only (no MUFU).
__device__ __forceinline__ float fast_exp(float s) {
    float t  = s * 1.44269504f;
    float fn = t + 12582912.0f;                 // 1.5*2^23 magic round-to-nearest
    float f  = t - (fn - 12582912.0f);          // f in [-0.5, 0.5]
    float p  = fmaf(0.009618129f, f, 0.05550411f);
    p = fmaf(p, f, 0.2402265f);
    p = fmaf(p, f, 0.6931472f);
    p = fmaf(p, f, 1.0f);
    return __int_as_float(__float_as_int(p) + (__float_as_int(fn) << 23));
}

// ---------------- small kernels ----------------
__global__ void k_lab(const unsigned int* __restrict__ raw) {
    __shared__ int is64;
    g_cnt[threadIdx.x] = 0;
    if (threadIdx.x == 0) {
        unsigned int nz = 0;
        for (int i = 1; i < 256; i += 2) nz |= raw[i];   // int64 high words all zero
        is64 = (nz == 0u) ? 1 : 0;
    }
    __syncthreads();
    int w64 = is64;
    for (int i = threadIdx.x; i < NROWS; i += blockDim.x) {
        int v = (w64 ? (int)raw[2 * i] : (int)raw[i]) & 1023;
        g_lab[i] = v;
        atomicAdd(&g_cnt[v], 1);
    }
}

__global__ void k_norm(const float* __restrict__ reps) {
    int row = blockIdx.x;
    if (threadIdx.x == 0) { g_pos[row] = 0.0f; g_neg[row] = 0.0f; }
    const float4* rp = (const float4*)(reps + (size_t)row * DIMS);
    float4 v = rp[threadIdx.x];
    float ss = v.x * v.x + v.y * v.y + v.z * v.z + v.w * v.w;
    #pragma unroll
    for (int o = 16; o; o >>= 1) ss += __shfl_xor_sync(0xffffffffu, ss, o);
    __shared__ float ws[4];
    if ((threadIdx.x & 31) == 0) ws[threadIdx.x >> 5] = ss;
    __syncthreads();
    float inv = rsqrtf(ws[0] + ws[1] + ws[2] + ws[3]);
    __nv_bfloat162 p0 = __floats2bfloat162_rn(v.x * inv, v.y * inv);
    __nv_bfloat162 p1 = __floats2bfloat162_rn(v.z * inv, v.w * inv);
    __nv_bfloat162* op = (__nv_bfloat162*)(g_A + (size_t)row * DIMS + threadIdx.x * 4);
    op[0] = p0; op[1] = p1;
}

// ---------------- fused wmma tile kernel ----------------
extern __shared__ char smem_raw[];

__global__ void __launch_bounds__(256, 2) k_gemm() {
    // linear block -> upper-triangular (bi, bj), bi <= bj
    int b = blockIdx.x, bi = 0, rem = b;
    while (rem >= NBLK - bi) { rem -= NBLK - bi; ++bi; }
    int bj = bi + rem;

    char* sb = smem_raw;
    uint32_t sb32 = smem_u32(sb);
    float* sE = (float*)sb;                 // epilogue tile aliases the stages
    __shared__ int labr[BM], labc[BM];

    int tid = threadIdx.x, wid = tid >> 5, lane = tid & 31;
    if (tid < 128) labr[tid] = g_lab[bi * BM + tid];
    else           labc[tid - 128] = g_lab[bj * BM + (tid - 128)];

    const char* Abase = (const char*)(g_A + (size_t)bi * BM * DIMS);
    const char* Bbase = (const char*)(g_A + (size_t)bj * BM * DIMS);

    // per-thread copy slice: row r (0..127), byte segment cs (0 or 64) of the 128B chunk
    int r  = tid >> 1;
    int cs = (tid & 1) * 64;

    // prefetch chunk 0 into stage 0
    {
        uint32_t dA = sb32 + r * 144 + cs;
        uint32_t dB = dA + BM * PAD_K * 2;
        const char* gA = Abase + (size_t)r * 1024 + cs;
        const char* gB = Bbase + (size_t)r * 1024 + cs;
        #pragma unroll
        for (int i = 0; i < 4; ++i) {
            cp16(dA + i * 16, gA + i * 16);
            cp16(dB + i * 16, gB + i * 16);
        }
        CP_COMMIT();
    }

    int w  = wid;
    int wm = w & 3;        // 4 warp rows (32 rows each)
    int wn = w >> 2;       // 2 warp cols (64 cols each)

    wmma::fragment<wmma::accumulator, 16, 16, 16, float> acc[2][4];
    #pragma unroll
    for (int m = 0; m < 2; ++m)
        #pragma unroll
        for (int n = 0; n < 4; ++n)
            wmma::fill_fragment(acc[m][n], 0.0f);

    for (int c = 0; c < 8; ++c) {
        int st = c & 1;
        if (c < 7) {   // prefetch next chunk into other stage
            uint32_t base = sb32 + (st ^ 1) * STAGE_BYTES;
            uint32_t dA = base + r * 144 + cs;
            uint32_t dB = dA + BM * PAD_K * 2;
            const char* gA = Abase + (size_t)r * 1024 + (c + 1) * 128 + cs;
            const char* gB = Bbase + (size_t)r * 1024 + (c + 1) * 128 + cs;
            #pragma unroll
            for (int i = 0; i < 4; ++i) {
                cp16(dA + i * 16, gA + i * 16);
                cp16(dB + i * 16, gB + i * 16);
            }
            CP_COMMIT();
            CP_WAIT1();
        } else {
            CP_WAIT0();
        }
        __syncthreads();

        const __nv_bfloat16* sA = (const __nv_bfloat16*)(sb + st * STAGE_BYTES);
        const __nv_bfloat16* sB = sA + BM * PAD_K;
        #pragma unroll
        for (int kk = 0; kk < BK; kk += 16) {
            wmma::fragment<wmma::matrix_a, 16, 16, 16, __nv_bfloat16, wmma::row_major> af[2];
            wmma::fragment<wmma::matrix_b, 16, 16, 16, __nv_bfloat16, wmma::col_major> bf[4];
            #pragma unroll
            for (int m = 0; m < 2; ++m)
                wmma::load_matrix_sync(af[m], &sA[(wm * 32 + m * 16) * PAD_K + kk], PAD_K);
            #pragma unroll
            for (int n = 0; n < 4; ++n)
                wmma::load_matrix_sync(bf[n], &sB[(wn * 64 + n * 16) * PAD_K + kk], PAD_K);
            #pragma unroll
            for (int m = 0; m < 2; ++m)
                #pragma unroll
                for (int n = 0; n < 4; ++n)
                    wmma::mma_sync(acc[m][n], af[m], bf[n], acc[m][n]);
        }
        __syncthreads();   // all warps done reading stage st before it is overwritten
    }

    // ---- epilogue: store cos tile (aliases stages; guarded by the loop-exit sync) ----
    #pragma unroll
    for (int m = 0; m < 2; ++m)
        #pragma unroll
        for (int n = 0; n < 4; ++n)
            wmma::store_matrix_sync(&sE[(wm * 32 + m * 16) * PAD_E + wn * 64 + n * 16],
                                    acc[m][n], PAD_E, wmma::mem_row_major);
    __syncthreads();

    bool isdiag = (bi == bj);

    // Phase A: row contributions; transform tile in place (s for same-label, e^s otherwise)
    {
        int rr = tid & 127, h = tid >> 7;
        int lr = labr[rr];
        float pos = 0.0f, neg = 0.0f;
        int cbase = h * 64;
        #pragma unroll 4
        for (int k = 0; k < 64; ++k) {
            int cc = cbase + k;
            float cosv = sE[rr * PAD_E + cc];
            float s = fmaf(cosv, 5.0f, 5.0000001f);   // ((1+cos)/2 + EPS)/TEMP, M = 0
            float v;
            if (lr == labc[cc]) {
                if (!(isdiag && rr == cc)) pos += s;
                v = s;
            } else {
                float e = fast_exp(s);
                neg += e;
                v = e;
            }
            if (!isdiag) sE[rr * PAD_E + cc] = v;
        }
        atomicAdd(&g_pos[bi * BM + rr], pos);
        atomicAdd(&g_neg[bi * BM + rr], neg);
    }

    // Phase B: column contributions via symmetry — pure adds, no recompute
    if (!isdiag) {
        __syncthreads();
        int cc = tid & 127, h = tid >> 7;
        int lc = labc[cc];
        float posc = 0.0f, negc = 0.0f;
        #pragma unroll 8
        for (int k = 0; k < 64; ++k) {
            int rr = h * 64 + k;
            float v = sE[rr * PAD_E + cc];
            if (labr[rr] == lc) posc += v; else negc += v;
        }
        atomicAdd(&g_pos[bj * BM + cc], posc);
        atomicAdd(&g_neg[bj * BM + cc], negc);
    }
}

// ---------------- final reduction ----------------
__global__ void k_final(float* __restrict__ out) {
    __shared__ float sl[256], sm[256];
    float lsum = 0.0f, msum = 0.0f;
    for (int i = threadIdx.x; i < NROWS; i += 256) {
        float cnt  = (float)(g_cnt[g_lab[i]] - 1);
        float posr = g_pos[i] / (cnt + 1e-8f);
        float loss = -posr + logf(g_neg[i] + 1e-8f);
        if (loss > 0.0f) { lsum += loss; msum += 1.0f; }
    }
    sl[threadIdx.x] = lsum; sm[threadIdx.x] = msum;
    __syncthreads();
    #pragma unroll
    for (int o = 128; o; o >>= 1) {
        if (threadIdx.x < o) { sl[threadIdx.x] += sl[threadIdx.x + o]; sm[threadIdx.x] += sm[threadIdx.x + o]; }
        __syncthreads();
    }
    if (threadIdx.x == 0) out[0] = sl[0] / (sm[0] + 1e-8f);
}

extern "C" void kernel_launch(void* const* d_in, const int* in_sizes, int n_in,
                              void* d_out, int out_size) {
    const float* reps = (const float*)d_in[0];
    const unsigned int* labraw = (const unsigned int*)d_in[1];
    float* out = (float*)d_out;

    cudaFuncSetAttribute(k_gemm, cudaFuncAttributeMaxDynamicSharedMemorySize, DSMEM);

    k_lab<<<1, 1024>>>(labraw);
    k_norm<<<NROWS, 128>>>(reps);
    k_gemm<<<NTILES, 256, DSMEM>>>();
    k_final<<<1, 256>>>(out);
}

// round 5
// speedup vs baseline: 1.5480x; 1.1770x over previous
#include <cuda_runtime.h>
#include <cuda_bf16.h>
#include <mma.h>
#include <cstdint>

using namespace nvcuda;

#define NROWS 8192
#define DIMS  512
#define BM    128
#define BK    64
#define NBLK  64                          /* 8192/128 */
#define NTILES 2080                       /* upper-triangular 64*65/2 */
#define PAD_K 72                          /* bf16 elems/row: 144B -> LDSM conflict-free */
#define PAD_E 132                         /* fp32 elems/row for epilogue (mult of 4) */
#define STAGE_BYTES (2 * BM * PAD_K * 2)  /* A+B per stage: 36864 B */
#define NSTAGE 3
#define DSMEM (NSTAGE * STAGE_BYTES)      /* 110592 B; epilogue tile (67584 B) aliases */

// ---------------- device scratch (no allocation allowed) ----------------
__device__ __nv_bfloat16 g_A[NROWS * DIMS];   // normalized reps, bf16
__device__ float g_pos[NROWS];
__device__ float g_neg[NROWS];
__device__ int   g_lab[NROWS];
__device__ int   g_cnt[1024];
__device__ float g_red[2];                    // masked loss sum, mask count

// ---------------- helpers ----------------
__device__ __forceinline__ uint32_t smem_u32(const void* p) {
    uint32_t a;
    asm("{ .reg .u64 t; cvta.to.shared.u64 t, %1; cvt.u32.u64 %0, t; }" : "=r"(a) : "l"(p));
    return a;
}
__device__ __forceinline__ void cp16(uint32_t dst, const void* src) {
    asm volatile("cp.async.cg.shared.global [%0], [%1], 16;" :: "r"(dst), "l"(src));
}
#define CP_COMMIT() asm volatile("cp.async.commit_group;" ::: "memory")
#define CP_WAIT1()  asm volatile("cp.async.wait_group 1;" ::: "memory")
#define CP_WAIT0()  asm volatile("cp.async.wait_group 0;" ::: "memory")

// fast exp(s): s in [-0.05, 10.1]; rel err ~6e-5. FMA/ALU pipes only (no MUFU).
__device__ __forceinline__ float fast_exp(float s) {
    float t  = s * 1.44269504f;
    float fn = t + 12582912.0f;                 // 1.5*2^23 magic round-to-nearest
    float f  = t - (fn - 12582912.0f);          // f in [-0.5, 0.5]
    float p  = fmaf(0.009618129f, f, 0.05550411f);
    p = fmaf(p, f, 0.2402265f);
    p = fmaf(p, f, 0.6931472f);
    p = fmaf(p, f, 1.0f);
    return __int_as_float(__float_as_int(p) + (__float_as_int(fn) << 23));
}

// ---------------- small kernels ----------------
__global__ void k_lab(const unsigned int* __restrict__ raw) {
    __shared__ unsigned s_nz;
    int tid = threadIdx.x;
    g_cnt[tid] = 0;
    if (tid < 2) g_red[tid] = 0.0f;
    if (tid == 0) s_nz = 0u;
    __syncthreads();
    // parallel int64-vs-int32 sniff: high words of first 512 entries
    unsigned my = (tid < 512) ? raw[2 * tid + 1] : 0u;
    #pragma unroll
    for (int o = 16; o; o >>= 1) my |= __shfl_xor_sync(0xffffffffu, my, o);
    if ((tid & 31) == 0 && my) atomicOr(&s_nz, my);
    __syncthreads();
    int w64 = (s_nz == 0u) ? 1 : 0;
    for (int i = tid; i < NROWS; i += blockDim.x) {
        int v = (w64 ? (int)raw[2 * i] : (int)raw[i]) & 1023;
        g_lab[i] = v;
        atomicAdd(&g_cnt[v], 1);
    }
}

__global__ void k_norm(const float* __restrict__ reps) {
    int row = blockIdx.x;
    if (threadIdx.x == 0) { g_pos[row] = 0.0f; g_neg[row] = 0.0f; }
    const float4* rp = (const float4*)(reps + (size_t)row * DIMS);
    float4 v = rp[threadIdx.x];
    float ss = v.x * v.x + v.y * v.y + v.z * v.z + v.w * v.w;
    #pragma unroll
    for (int o = 16; o; o >>= 1) ss += __shfl_xor_sync(0xffffffffu, ss, o);
    __shared__ float ws[4];
    if ((threadIdx.x & 31) == 0) ws[threadIdx.x >> 5] = ss;
    __syncthreads();
    float inv = rsqrtf(ws[0] + ws[1] + ws[2] + ws[3]);
    __nv_bfloat162 p0 = __floats2bfloat162_rn(v.x * inv, v.y * inv);
    __nv_bfloat162 p1 = __floats2bfloat162_rn(v.z * inv, v.w * inv);
    __nv_bfloat162* op = (__nv_bfloat162*)(g_A + (size_t)row * DIMS + threadIdx.x * 4);
    op[0] = p0; op[1] = p1;
}

// ---------------- fused wmma tile kernel ----------------
extern __shared__ char smem_raw[];

__global__ void __launch_bounds__(256, 2) k_gemm() {
    // linear block -> upper-triangular (bi, bj), bi <= bj
    int b = blockIdx.x, bi = 0, rem = b;
    while (rem >= NBLK - bi) { rem -= NBLK - bi; ++bi; }
    int bj = bi + rem;

    char* sb = smem_raw;
    uint32_t sb32 = smem_u32(sb);
    float* sE = (float*)sb;                 // epilogue tile aliases the stages
    __shared__ int labr[BM], labc[BM];

    int tid = threadIdx.x, wid = tid >> 5;
    if (tid < 128) labr[tid] = g_lab[bi * BM + tid];
    else           labc[tid - 128] = g_lab[bj * BM + (tid - 128)];

    const char* Abase = (const char*)(g_A + (size_t)bi * BM * DIMS);
    const char* Bbase = (const char*)(g_A + (size_t)bj * BM * DIMS);

    // per-thread copy slice: row r (0..127), byte segment cs (0 or 64) of the 128B chunk
    int r  = tid >> 1;
    int cs = (tid & 1) * 64;
    uint32_t dA0 = sb32 + r * 144 + cs;
    const char* gA0 = Abase + (size_t)r * 1024 + cs;
    const char* gB0 = Bbase + (size_t)r * 1024 + cs;

    // prefetch chunks 0,1 into stages 0,1
    #pragma unroll
    for (int c = 0; c < 2; ++c) {
        uint32_t dA = dA0 + c * STAGE_BYTES;
        #pragma unroll
        for (int i = 0; i < 4; ++i) {
            cp16(dA + i * 16,                 gA0 + c * 128 + i * 16);
            cp16(dA + 18432 + i * 16,         gB0 + c * 128 + i * 16);
        }
        CP_COMMIT();
    }

    int wm = wid & 3;        // 4 warp rows (32 rows each)
    int wn = wid >> 2;       // 2 warp cols (64 cols each)

    wmma::fragment<wmma::accumulator, 16, 16, 16, float> acc[2][4];
    #pragma unroll
    for (int m = 0; m < 2; ++m)
        #pragma unroll
        for (int n = 0; n < 4; ++n)
            wmma::fill_fragment(acc[m][n], 0.0f);

    #pragma unroll
    for (int c = 0; c < 8; ++c) {
        if (c < 7) CP_WAIT1(); else CP_WAIT0();   // chunk c resident
        __syncthreads();                          // all warps done with chunk c-1
        if (c + 2 < 8) {                          // prefetch c+2 into stage (c+2)%3 (free: stage (c-1)%3)
            uint32_t dA = dA0 + ((c + 2) % NSTAGE) * STAGE_BYTES;
            #pragma unroll
            for (int i = 0; i < 4; ++i) {
                cp16(dA + i * 16,         gA0 + (c + 2) * 128 + i * 16);
                cp16(dA + 18432 + i * 16, gB0 + (c + 2) * 128 + i * 16);
            }
            CP_COMMIT();
        }
        const __nv_bfloat16* sA = (const __nv_bfloat16*)(sb + (c % NSTAGE) * STAGE_BYTES);
        const __nv_bfloat16* sB = sA + BM * PAD_K;
        #pragma unroll
        for (int kk = 0; kk < BK; kk += 16) {
            wmma::fragment<wmma::matrix_a, 16, 16, 16, __nv_bfloat16, wmma::row_major> af[2];
            wmma::fragment<wmma::matrix_b, 16, 16, 16, __nv_bfloat16, wmma::col_major> bf[4];
            #pragma unroll
            for (int m = 0; m < 2; ++m)
                wmma::load_matrix_sync(af[m], &sA[(wm * 32 + m * 16) * PAD_K + kk], PAD_K);
            #pragma unroll
            for (int n = 0; n < 4; ++n)
                wmma::load_matrix_sync(bf[n], &sB[(wn * 64 + n * 16) * PAD_K + kk], PAD_K);
            #pragma unroll
            for (int m = 0; m < 2; ++m)
                #pragma unroll
                for (int n = 0; n < 4; ++n)
                    wmma::mma_sync(acc[m][n], af[m], bf[n], acc[m][n]);
        }
    }
    __syncthreads();   // last stage fully consumed before sE overwrite

    // ---- epilogue: store cos tile (aliases the stages) ----
    #pragma unroll
    for (int m = 0; m < 2; ++m)
        #pragma unroll
        for (int n = 0; n < 4; ++n)
            wmma::store_matrix_sync(&sE[(wm * 32 + m * 16) * PAD_E + wn * 64 + n * 16],
                                    acc[m][n], PAD_E, wmma::mem_row_major);
    __syncthreads();

    bool isdiag = (bi == bj);

    // Phase A: row contributions; transform tile in place (s for same-label, e^s otherwise)
    {
        int rr = tid & 127, h = tid >> 7;
        int lr = labr[rr];
        float pos = 0.0f, neg = 0.0f;
        int cbase = h * 64;
        float4* rowp = (float4*)&sE[rr * PAD_E + cbase];
        #pragma unroll 4
        for (int k4 = 0; k4 < 16; ++k4) {
            float4 v = rowp[k4];
            float* vp = (float*)&v;
            #pragma unroll
            for (int q = 0; q < 4; ++q) {
                int cc = cbase + k4 * 4 + q;
                float s = fmaf(vp[q], 5.0f, 5.0000001f);   // ((1+cos)/2 + EPS)/TEMP, M = 0
                if (lr == labc[cc]) {
                    if (!(isdiag && rr == cc)) pos += s;
                    vp[q] = s;
                } else {
                    float e = fast_exp(s);
                    neg += e;
                    vp[q] = e;
                }
            }
            if (!isdiag) rowp[k4] = v;
        }
        atomicAdd(&g_pos[bi * BM + rr], pos);
        atomicAdd(&g_neg[bi * BM + rr], neg);
    }

    // Phase B: column contributions via symmetry — pure adds, no recompute
    if (!isdiag) {
        __syncthreads();
        int cc = tid & 127, h = tid >> 7;
        int lc = labc[cc];
        float posc = 0.0f, negc = 0.0f;
        #pragma unroll 8
        for (int k = 0; k < 64; ++k) {
            int rr = h * 64 + k;
            float v = sE[rr * PAD_E + cc];
            if (labr[rr] == lc) posc += v; else negc += v;
        }
        atomicAdd(&g_pos[bj * BM + cc], posc);
        atomicAdd(&g_neg[bj * BM + cc], negc);
    }
}

// ---------------- final reduction (parallel) ----------------
__global__ void k_final1() {
    __shared__ float sl[256], sm[256];
    int i = blockIdx.x * 256 + threadIdx.x;   // 32 blocks x 256 = 8192
    float lsum = 0.0f, msum = 0.0f;
    #pragma unroll
    for (int rep = 0; rep < NROWS / (32 * 256); ++rep, i += 32 * 256) {
        float cnt  = (float)(g_cnt[g_lab[i]] - 1);
        float posr = g_pos[i] / (cnt + 1e-8f);
        float loss = -posr + logf(g_neg[i] + 1e-8f);
        if (loss > 0.0f) { lsum += loss; msum += 1.0f; }
    }
    sl[threadIdx.x] = lsum; sm[threadIdx.x] = msum;
    __syncthreads();
    #pragma unroll
    for (int o = 128; o; o >>= 1) {
        if (threadIdx.x < o) { sl[threadIdx.x] += sl[threadIdx.x + o]; sm[threadIdx.x] += sm[threadIdx.x + o]; }
        __syncthreads();
    }
    if (threadIdx.x == 0) { atomicAdd(&g_red[0], sl[0]); atomicAdd(&g_red[1], sm[0]); }
}
__global__ void k_final2(float* __restrict__ out) {
    out[0] = g_red[0] / (g_red[1] + 1e-8f);
}

extern "C" void kernel_launch(void* const* d_in, const int* in_sizes, int n_in,
                              void* d_out, int out_size) {
    const float* reps = (const float*)d_in[0];
    const unsigned int* labraw = (const unsigned int*)d_in[1];
    float* out = (float*)d_out;

    cudaFuncSetAttribute(k_gemm, cudaFuncAttributeMaxDynamicSharedMemorySize, DSMEM);

    k_lab<<<1, 1024>>>(labraw);
    k_norm<<<NROWS, 128>>>(reps);
    k_gemm<<<NTILES, 256, DSMEM>>>();
    k_final1<<<32, 256>>>();
    k_final2<<<1, 1>>>(out);
}

// round 7
// speedup vs baseline: 1.6566x; 1.0701x over previous
#include <cuda_runtime.h>
#include <cuda_bf16.h>
#include <cstdint>

#define NROWS 8192
#define DIMS  512
#define BM    128
#define BK    64
#define NBLK  64                          /* 8192/128 */
#define NTILES 2080                       /* upper-triangular 64*65/2 */
#define PAD_K 72                          /* bf16 elems/row: 144B -> LDSM conflict-free */
#define A_BYTES (BM * PAD_K * 2)          /* 18432 */
#define STAGE_BYTES (2 * A_BYTES)         /* A+B per stage: 36864 B */
#define NSTAGE 3
#define DSMEM (NSTAGE * STAGE_BYTES)      /* 110592 B */

// ---------------- device scratch (no allocation allowed) ----------------
__device__ __nv_bfloat16 g_A[NROWS * DIMS];   // normalized reps, bf16
__device__ float g_pos[NROWS];
__device__ float g_neg[NROWS];
__device__ int   g_lab[NROWS];
__device__ int   g_cnt[1024];
__device__ float g_red[2];                    // masked loss sum, mask count
__device__ int   g_tick;

// ---------------- helpers ----------------
__device__ __forceinline__ uint32_t smem_u32(const void* p) {
    uint32_t a;
    asm("{ .reg .u64 t; cvta.to.shared.u64 t, %1; cvt.u32.u64 %0, t; }" : "=r"(a) : "l"(p));
    return a;
}
__device__ __forceinline__ void cp16(uint32_t dst, const void* src) {
    asm volatile("cp.async.cg.shared.global [%0], [%1], 16;" :: "r"(dst), "l"(src));
}
#define CP_COMMIT() asm volatile("cp.async.commit_group;" ::: "memory")
#define CP_WAIT1()  asm volatile("cp.async.wait_group 1;" ::: "memory")
#define CP_WAIT0()  asm volatile("cp.async.wait_group 0;" ::: "memory")

__device__ __forceinline__ void ldsm4(uint32_t addr, uint32_t& r0, uint32_t& r1,
                                      uint32_t& r2, uint32_t& r3) {
    asm volatile("ldmatrix.sync.aligned.m8n8.x4.shared.b16 {%0,%1,%2,%3}, [%4];"
        : "=r"(r0), "=r"(r1), "=r"(r2), "=r"(r3) : "r"(addr));
}
__device__ __forceinline__ void mma16816(float* d, uint32_t a0, uint32_t a1,
                                         uint32_t a2, uint32_t a3,
                                         uint32_t b0, uint32_t b1) {
    asm volatile("mma.sync.aligned.m16n8k16.row.col.f32.bf16.bf16.f32 "
        "{%0,%1,%2,%3}, {%4,%5,%6,%7}, {%8,%9}, {%0,%1,%2,%3};"
        : "+f"(d[0]), "+f"(d[1]), "+f"(d[2]), "+f"(d[3])
        : "r"(a0), "r"(a1), "r"(a2), "r"(a3), "r"(b0), "r"(b1));
}

// fast exp(s): s in [-0.05, 10.1]; rel err ~6e-5. FMA/ALU pipes only (no MUFU).
__device__ __forceinline__ float fast_exp(float s) {
    float t  = s * 1.44269504f;
    float fn = t + 12582912.0f;                 // 1.5*2^23 magic round-to-nearest
    float f  = t - (fn - 12582912.0f);          // f in [-0.5, 0.5]
    float p  = fmaf(0.009618129f, f, 0.05550411f);
    p = fmaf(p, f, 0.2402265f);
    p = fmaf(p, f, 0.6931472f);
    p = fmaf(p, f, 1.0f);
    return __int_as_float(__float_as_int(p) + (__float_as_int(fn) << 23));
}
__device__ __forceinline__ float red4(float v) {     // sum over lane&3 group
    v += __shfl_xor_sync(0xffffffffu, v, 1);
    v += __shfl_xor_sync(0xffffffffu, v, 2);
    return v;
}
__device__ __forceinline__ float red8(float v) {     // sum over lane>>2 group
    v += __shfl_xor_sync(0xffffffffu, v, 4);
    v += __shfl_xor_sync(0xffffffffu, v, 8);
    v += __shfl_xor_sync(0xffffffffu, v, 16);
    return v;
}

// ---------------- small kernels ----------------
__global__ void k_lab(const unsigned int* __restrict__ raw) {
    __shared__ unsigned s_nz;
    int tid = threadIdx.x;
    g_cnt[tid] = 0;
    if (tid < 2) g_red[tid] = 0.0f;
    if (tid == 0) { s_nz = 0u; g_tick = 0; }
    __syncthreads();
    unsigned my = (tid < 512) ? raw[2 * tid + 1] : 0u;   // int64 high words
    #pragma unroll
    for (int o = 16; o; o >>= 1) my |= __shfl_xor_sync(0xffffffffu, my, o);
    if ((tid & 31) == 0 && my) atomicOr(&s_nz, my);
    __syncthreads();
    int w64 = (s_nz == 0u) ? 1 : 0;
    for (int i = tid; i < NROWS; i += blockDim.x) {
        int v = (w64 ? (int)raw[2 * i] : (int)raw[i]) & 1023;
        g_lab[i] = v;
        atomicAdd(&g_cnt[v], 1);
    }
}

__global__ void k_norm(const float* __restrict__ reps) {
    int row = blockIdx.x;
    if (threadIdx.x == 0) { g_pos[row] = 0.0f; g_neg[row] = 0.0f; }
    const float4* rp = (const float4*)(reps + (size_t)row * DIMS);
    float4 v = rp[threadIdx.x];
    float ss = v.x * v.x + v.y * v.y + v.z * v.z + v.w * v.w;
    #pragma unroll
    for (int o = 16; o; o >>= 1) ss += __shfl_xor_sync(0xffffffffu, ss, o);
    __shared__ float ws[4];
    if ((threadIdx.x & 31) == 0) ws[threadIdx.x >> 5] = ss;
    __syncthreads();
    float inv = rsqrtf(ws[0] + ws[1] + ws[2] + ws[3]);
    __nv_bfloat162 p0 = __floats2bfloat162_rn(v.x * inv, v.y * inv);
    __nv_bfloat162 p1 = __floats2bfloat162_rn(v.z * inv, v.w * inv);
    __nv_bfloat162* op = (__nv_bfloat162*)(g_A + (size_t)row * DIMS + threadIdx.x * 4);
    op[0] = p0; op[1] = p1;
}

// ---------------- fused mma.sync tile kernel, register epilogue ----------------
extern __shared__ char smem_raw[];

__global__ void __launch_bounds__(256, 2) k_gemm() {
    // linear block -> upper-triangular (bi, bj), bi <= bj
    int b = blockIdx.x, bi = 0, rem = b;
    while (rem >= NBLK - bi) { rem -= NBLK - bi; ++bi; }
    int bj = bi + rem;

    char* sb = smem_raw;
    uint32_t sb32 = smem_u32(sb);
    __shared__ int labr[BM], labc[BM];

    int tid = threadIdx.x, wid = tid >> 5, lane = tid & 31;
    if (tid < 128) labr[tid] = g_lab[bi * BM + tid];
    else           labc[tid - 128] = g_lab[bj * BM + (tid - 128)];

    const char* Abase = (const char*)(g_A + (size_t)bi * BM * DIMS);
    const char* Bbase = (const char*)(g_A + (size_t)bj * BM * DIMS);

    // copy slice: row r (0..127), byte segment cs (0 or 64) of each 128B chunk
    int r  = tid >> 1;
    int cs = (tid & 1) * 64;
    uint32_t dA0 = sb32 + r * 144 + cs;
    const char* gA0 = Abase + (size_t)r * 1024 + cs;
    const char* gB0 = Bbase + (size_t)r * 1024 + cs;

    #pragma unroll
    for (int c = 0; c < 2; ++c) {     // prefetch chunks 0,1 into stages 0,1
        uint32_t dA = dA0 + c * STAGE_BYTES;
        #pragma unroll
        for (int i = 0; i < 4; ++i) {
            cp16(dA + i * 16,           gA0 + c * 128 + i * 16);
            cp16(dA + A_BYTES + i * 16, gB0 + c * 128 + i * 16);
        }
        CP_COMMIT();
    }

    int wm = wid & 3;        // 4 warp rows (32 rows each)
    int wn = wid >> 2;       // 2 warp cols (64 cols each)

    float acc[2][8][4];
    #pragma unroll
    for (int mt = 0; mt < 2; ++mt)
        #pragma unroll
        for (int nt = 0; nt < 8; ++nt)
            acc[mt][nt][0] = acc[mt][nt][1] = acc[mt][nt][2] = acc[mt][nt][3] = 0.0f;

    // ldmatrix lane address components (within a stage)
    uint32_t aRow = (uint32_t)(wm * 32 + (lane & 15));          // + mt*16
    uint32_t aOff = aRow * 144 + (lane >> 4) * 16;              // + kk*2
    uint32_t bRow = (uint32_t)(wn * 64 + ((lane >> 4) & 1) * 8 + (lane & 7));  // + ntp*16
    uint32_t bOff = A_BYTES + bRow * 144 + ((lane >> 3) & 1) * 16;             // + kk*2

    int sc = 0;
    for (int c = 0; c < 8; ++c) {
        if (c < 7) CP_WAIT1(); else CP_WAIT0();
        __syncthreads();                          // prior chunk fully consumed
        if (c + 2 < 8) {
            int sp = sc + 2; if (sp >= NSTAGE) sp -= NSTAGE;
            uint32_t dA = dA0 + sp * STAGE_BYTES;
            const char* gA = gA0 + (c + 2) * 128;
            const char* gB = gB0 + (c + 2) * 128;
            #pragma unroll
            for (int i = 0; i < 4; ++i) {
                cp16(dA + i * 16,           gA + i * 16);
                cp16(dA + A_BYTES + i * 16, gB + i * 16);
            }
            CP_COMMIT();
        }
        uint32_t stg = sb32 + sc * STAGE_BYTES;
        #pragma unroll
        for (int kk = 0; kk < 4; ++kk) {          // 4 k16-steps per 64-chunk
            uint32_t a[2][4], bf[8][2];
            #pragma unroll
            for (int mt = 0; mt < 2; ++mt)
                ldsm4(stg + aOff + mt * 16 * 144 + kk * 32,
                      a[mt][0], a[mt][1], a[mt][2], a[mt][3]);
            #pragma unroll
            for (int ntp = 0; ntp < 4; ++ntp)
                ldsm4(stg + bOff + ntp * 16 * 144 + kk * 32,
                      bf[ntp * 2][0], bf[ntp * 2][1], bf[ntp * 2 + 1][0], bf[ntp * 2 + 1][1]);
            #pragma unroll
            for (int mt = 0; mt < 2; ++mt)
                #pragma unroll
                for (int nt = 0; nt < 8; ++nt)
                    mma16816(acc[mt][nt], a[mt][0], a[mt][1], a[mt][2], a[mt][3],
                             bf[nt][0], bf[nt][1]);
        }
        ++sc; if (sc >= NSTAGE) sc = 0;
    }

    // ---- register epilogue: rows + columns in one pass, exp computed once ----
    bool isdiag = (bi == bj);
    int lr[4], lc[16];
    #pragma unroll
    for (int mt = 0; mt < 2; ++mt)
        #pragma unroll
        for (int h = 0; h < 2; ++h)
            lr[mt * 2 + h] = labr[wm * 32 + mt * 16 + h * 8 + (lane >> 2)];
    #pragma unroll
    for (int nt = 0; nt < 8; ++nt)
        #pragma unroll
        for (int q = 0; q < 2; ++q)
            lc[nt * 2 + q] = labc[wn * 64 + nt * 8 + 2 * (lane & 3) + q];

    float rpos[4] = {0, 0, 0, 0}, rneg[4] = {0, 0, 0, 0};
    float cpos[16], cneg[16];
    #pragma unroll
    for (int i = 0; i < 16; ++i) { cpos[i] = 0.0f; cneg[i] = 0.0f; }

    #pragma unroll
    for (int mt = 0; mt < 2; ++mt)
        #pragma unroll
        for (int nt = 0; nt < 8; ++nt)
            #pragma unroll
            for (int e = 0; e < 4; ++e) {
                int h = e >> 1, q = e & 1;
                float s = fmaf(acc[mt][nt][e], 5.0f, 5.0000001f);  // ((1+cos)/2+EPS)/TEMP
                if (lr[mt * 2 + h] == lc[nt * 2 + q]) {
                    int rr = wm * 32 + mt * 16 + h * 8 + (lane >> 2);
                    int cc = wn * 64 + nt * 8 + 2 * (lane & 3) + q;
                    if (!(isdiag && rr == cc)) rpos[mt * 2 + h] += s;
                    cpos[nt * 2 + q] += s;
                } else {
                    float ex = fast_exp(s);
                    rneg[mt * 2 + h] += ex;
                    cneg[nt * 2 + q] += ex;
                }
            }

    // row scatter (always)
    #pragma unroll
    for (int i = 0; i < 4; ++i) {
        float p = red4(rpos[i]), n = red4(rneg[i]);
        if ((lane & 3) == 0) {
            int rr = bi * BM + wm * 32 + (i >> 1) * 16 + (i & 1) * 8 + (lane >> 2);
            atomicAdd(&g_pos[rr], p);
            atomicAdd(&g_neg[rr], n);
        }
    }
    // column scatter via symmetry (off-diag tiles only)
    if (!isdiag) {
        #pragma unroll
        for (int sl = 0; sl < 16; ++sl) {
            float p = red8(cpos[sl]), n = red8(cneg[sl]);
            if (lane < 4) {
                int cc = bj * BM + wn * 64 + (sl >> 1) * 8 + 2 * lane + (sl & 1);
                atomicAdd(&g_pos[cc], p);
                atomicAdd(&g_neg[cc], n);
            }
        }
    }
}

// ---------------- final reduction (parallel, self-finishing) ----------------
__global__ void k_final1(float* __restrict__ out) {
    __shared__ float sl[256], sm[256];
    int i = blockIdx.x * 256 + threadIdx.x;   // 32 blocks x 256 = 8192
    float cnt  = (float)(g_cnt[g_lab[i]] - 1);
    float posr = g_pos[i] / (cnt + 1e-8f);
    float loss = -posr + logf(g_neg[i] + 1e-8f);
    float lsum = 0.0f, msum = 0.0f;
    if (loss > 0.0f) { lsum = loss; msum = 1.0f; }
    sl[threadIdx.x] = lsum; sm[threadIdx.x] = msum;
    __syncthreads();
    #pragma unroll
    for (int o = 128; o; o >>= 1) {
        if (threadIdx.x < o) { sl[threadIdx.x] += sl[threadIdx.x + o]; sm[threadIdx.x] += sm[threadIdx.x + o]; }
        __syncthreads();
    }
    if (threadIdx.x == 0) {
        atomicAdd(&g_red[0], sl[0]);
        atomicAdd(&g_red[1], sm[0]);
        __threadfence();
        if (atomicAdd(&g_tick, 1) == 31)
            out[0] = g_red[0] / (g_red[1] + 1e-8f);
    }
}

extern "C" void kernel_launch(void* const* d_in, const int* in_sizes, int n_in,
                              void* d_out, int out_size) {
    const float* reps = (const float*)d_in[0];
    const unsigned int* labraw = (const unsigned int*)d_in[1];
    float* out = (float*)d_out;

    cudaFuncSetAttribute(k_gemm, cudaFuncAttributeMaxDynamicSharedMemorySize, DSMEM);

    k_lab<<<1, 1024>>>(labraw);
    k_norm<<<NROWS, 128>>>(reps);
    k_gemm<<<NTILES, 256, DSMEM>>>();
    k_final1<<<32, 256>>>(out);
}